// round 3
// baseline (speedup 1.0000x reference)
#include <cuda_runtime.h>
#include <cuda_bf16.h>
#include <math.h>

#define FULLMASK 0xFFFFFFFFu

// Problem constants (fixed by the dataset)
#define NMAX   16384
#define INCH   128
#define SDIM   4
#define PDIM   64
#define OUTCH  128
#define KNN    50
#define NPER   4096   // nodes per segment (16384 / 4 splits)

// ---------------- device scratch (no allocation allowed) ----------------
__device__ float g_space[NMAX * SDIM];
__device__ float g_prop [NMAX * PDIM];
__device__ int   g_idx  [NMAX * KNN];
__device__ float g_d2   [NMAX * KNN];

// Bit-exact replication of XLA arithmetic:
//   sq  : multiply then linear reduce (no fma)
//   dot : cublas-style ascending-k fma chain starting from 0
__device__ __forceinline__ float xla_sq4(float4 c) {
    return __fadd_rn(__fadd_rn(__fadd_rn(__fmul_rn(c.x, c.x), __fmul_rn(c.y, c.y)),
                               __fmul_rn(c.z, c.z)),
                     __fmul_rn(c.w, c.w));
}
__device__ __forceinline__ float cublas_dot4(float4 a, float4 b) {
    return __fmaf_rn(a.w, b.w, __fmaf_rn(a.z, b.z, __fmaf_rn(a.y, b.y, __fmul_rn(a.x, b.x))));
}

// ---------------- K1: space = x@Ws + bs ; prop = x@Wp + bp ----------------
// 16 nodes per block, 256 threads.
// space emulates cuBLAS skinny-gemm "sliced1x4": k split into 4 contiguous
// slices of 32, each a serial fma chain from 0, combined linearly, then the
// bias added as a separate RN op (XLA epilogue fusion).
__global__ void k1_project(const float* __restrict__ x,
                           const float* __restrict__ Ws, const float* __restrict__ bs,
                           const float* __restrict__ Wp, const float* __restrict__ bp) {
    __shared__ float sWp[INCH * PDIM];   // 32 KB
    __shared__ float sWs[INCH * SDIM];   // 2 KB
    __shared__ float sx[16 * INCH];      // 8 KB
    const int tid = threadIdx.x;
    for (int i = tid; i < INCH * PDIM; i += 256) sWp[i] = Wp[i];
    for (int i = tid; i < INCH * SDIM; i += 256) sWs[i] = Ws[i];
    const int base = blockIdx.x * 16;
    for (int i = tid; i < 16 * INCH; i += 256) sx[i] = x[(size_t)base * INCH + i];
    __syncthreads();

    for (int o = tid; o < 16 * (PDIM + SDIM); o += 256) {
        const int node = o / (PDIM + SDIM);
        const int c    = o - node * (PDIM + SDIM);
        const float* xr = &sx[node * INCH];
        const int gn = base + node;
        if (c < PDIM) {
            float acc = bp[c];
            #pragma unroll 8
            for (int kk = 0; kk < INCH; kk++) acc = __fmaf_rn(xr[kk], sWp[kk * PDIM + c], acc);
            g_prop[(size_t)gn * PDIM + c] = acc;
        } else {
            const int cs = c - PDIM;
            float s[4];
            #pragma unroll
            for (int sl = 0; sl < 4; sl++) {
                float acc = 0.0f;
                const int k0 = sl * 32;
                #pragma unroll
                for (int kk = 0; kk < 32; kk++)
                    acc = __fmaf_rn(xr[k0 + kk], sWs[(k0 + kk) * SDIM + cs], acc);
                s[sl] = acc;
            }
            const float g = __fadd_rn(__fadd_rn(__fadd_rn(s[0], s[1]), s[2]), s[3]);
            g_space[(size_t)gn * SDIM + cs] = __fadd_rn(g, bs[cs]);
        }
    }
}

// ---------------- K2: exact KNN via per-warp radix select ----------------
// Block = 256 threads = 8 warps = 8 queries. Dynamic smem:
//   bits  : 8 * 4096 u32  (131072 B)
//   hist  : 8 * 256  u32  (  8192 B)
//   sortk : 8 * 64   u64  (  4096 B)
//   eqk   : 8 * 64   u64  (  4096 B)
#define K2_SMEM (8*4096*4 + 8*256*4 + 8*64*8 + 8*64*8)

__global__ void k2_knn() {
    extern __shared__ unsigned char dsm[];
    unsigned*           bits  = (unsigned*)dsm;
    unsigned*           hist  = (unsigned*)(dsm + 8*4096*4);
    unsigned long long* sortk = (unsigned long long*)(dsm + 8*4096*4 + 8*256*4);
    unsigned long long* eqk   = sortk + 8*64;

    __shared__ __align__(16) float qc[8][4];
    __shared__ float qsq[8];

    const int tid = threadIdx.x;
    const int q0 = blockIdx.x * 8;
    const int segBase = (q0 / NPER) * NPER;

    if (tid < 32) {
        const int q = tid >> 2, d = tid & 3;
        qc[q][d] = g_space[(size_t)(q0 + q) * 4 + d];
    }
    __syncthreads();
    if (tid < 8) {
        qsq[tid] = xla_sq4(*(const float4*)qc[tid]);
    }
    __syncthreads();

    // Phase A: all 4096 clamped squared distances for all 8 queries,
    // bit-exact vs reference: d2 = RN( RN(sq_i + sq_j) - 2*dot ), clamp 0.
    for (int j = tid; j < NPER; j += 256) {
        const float4 cj = *(const float4*)&g_space[(size_t)(segBase + j) * 4];
        const float sqj = xla_sq4(cj);
        #pragma unroll
        for (int q = 0; q < 8; q++) {
            const float4 cq = *(const float4*)qc[q];
            const float dot = cublas_dot4(cq, cj);
            const float t   = __fadd_rn(qsq[q], sqj);
            float d2 = __fadd_rn(t, __fmul_rn(-2.0f, dot));
            d2 = fmaxf(d2, 0.0f);
            bits[q * NPER + j] = __float_as_uint(d2);
        }
    }
    __syncthreads();

    // Phase B: warp w selects top-50 for query q0+w.
    const int w = tid >> 5, lane = tid & 31;
    unsigned* wb = bits + w * NPER;
    unsigned* h  = hist + w * 256;
    unsigned long long* sk = sortk + w * 64;
    unsigned long long* ek = eqk   + w * 64;
    const int gq = q0 + w;

    unsigned k = KNN, prefix = 0;
    for (int round = 0; round < 4; round++) {
        const int shift = 24 - 8 * round;
        const unsigned hiMask = (round == 0) ? 0u : (0xFFFFFFFFu << (shift + 8));
        for (int b = lane; b < 256; b += 32) h[b] = 0;
        __syncwarp();
        for (int j = lane; j < NPER; j += 32) {
            const unsigned v = wb[j];
            if ((v & hiMask) == prefix) atomicAdd(&h[(v >> shift) & 255], 1u);
        }
        __syncwarp();
        // parallel digit find: 8 bins per lane + warp scan
        unsigned binv[8]; unsigned s = 0;
        #pragma unroll
        for (int b = 0; b < 8; b++) { binv[b] = h[lane * 8 + b]; s += binv[b]; }
        unsigned cum = s;
        #pragma unroll
        for (int off = 1; off < 32; off <<= 1) {
            const unsigned v = __shfl_up_sync(FULLMASK, cum, off);
            if (lane >= off) cum += v;
        }
        const unsigned m = __ballot_sync(FULLMASK, cum >= k);
        const int tl = __ffs(m) - 1;
        unsigned digit = 0, kk = k;
        if (lane == tl) {
            unsigned cb = cum - s;
            #pragma unroll
            for (int b = 0; b < 8; b++) {
                if (cb + binv[b] >= kk) { digit = (unsigned)(lane * 8 + b); kk -= cb; break; }
                cb += binv[b];
            }
        }
        digit = __shfl_sync(FULLMASK, digit, tl);
        k     = __shfl_sync(FULLMASK, kk, tl);
        prefix |= (digit << shift);
        __syncwarp();
    }
    const unsigned T = prefix;          // exact 50th smallest value
    const unsigned lmlt = (1u << lane) - 1u;

    // Ordered collection of (<T) and (==T) candidates (index-ascending).
    unsigned nless = 0, neq = 0;
    for (int base = 0; base < NPER; base += 32) {
        const int j = base + lane;
        const unsigned v = wb[j];
        const bool lt = (v < T), eqv = (v == T);
        const unsigned ml = __ballot_sync(FULLMASK, lt);
        const unsigned me = __ballot_sync(FULLMASK, eqv);
        if (lt) {
            const unsigned p = nless + __popc(ml & lmlt);
            if (p < 64) sk[p] = ((unsigned long long)v << 32) | (unsigned)j;
        }
        if (eqv) {
            const unsigned p = neq + __popc(me & lmlt);
            if (p < 64) ek[p] = ((unsigned long long)v << 32) | (unsigned)j;
        }
        nless += __popc(ml); neq += __popc(me);
    }
    __syncwarp();

    unsigned cl = nless; if (cl > KNN) cl = KNN;   // safety
    for (int m = lane; m < 64; m += 32) {
        if (m >= (int)cl) {
            sk[m] = (m < KNN) ? ek[m - cl] : 0xFFFFFFFFFFFFFFFFull;
        }
    }
    __syncwarp();

    // Rank sort (keys strictly distinct: idx in low bits).
    #pragma unroll
    for (int mm = 0; mm < 2; mm++) {
        const int m = lane + mm * 32;
        const unsigned long long km = sk[m];
        if (km != 0xFFFFFFFFFFFFFFFFull) {
            int rank = 0;
            for (int n = 0; n < 64; n++) rank += (sk[n] < km) ? 1 : 0;
            if (rank < KNN) {
                g_idx[(size_t)gq * KNN + rank] = segBase + (int)(km & 0xFFFFFFFFull);
                g_d2 [(size_t)gq * KNN + rank] = __uint_as_float((unsigned)(km >> 32));
            }
        }
    }
}

// ---------------- K3: gather + mean/max + output GEMM + relu ----------------
// 16 nodes per block, 128 threads.
__global__ void k3_aggregate(const float* __restrict__ x,
                             const float* __restrict__ Wo, const float* __restrict__ bo,
                             float* __restrict__ out) {
    __shared__ __align__(16) float feat[16][2 * PDIM + INCH];   // 16x256
    __shared__ float warr[KNN];
    __shared__ int   gidx[KNN];
    __shared__ float accA[PDIM], mxA[PDIM];

    const int tid = threadIdx.x;
    const int base = blockIdx.x * 16;

    for (int t = 0; t < 16; t++) {
        const int i = base + t;
        if (tid < KNN) {
            warr[tid] = expf(-10.0f * g_d2[(size_t)i * KNN + tid]);
            gidx[tid] = g_idx[(size_t)i * KNN + tid];
        }
        feat[t][tid] = x[(size_t)i * INCH + tid];
        __syncthreads();

        const int half = tid >> 6, c = tid & 63;
        float acc = 0.0f, mx = -INFINITY;
        for (int r = half; r < KNN; r += 2) {
            const float v = g_prop[(size_t)gidx[r] * PDIM + c] * warr[r];
            acc += v; mx = fmaxf(mx, v);
        }
        if (half == 0) { accA[c] = acc; mxA[c] = mx; }
        __syncthreads();
        if (half == 1) {
            feat[t][INCH + c]        = (accA[c] + acc) * (1.0f / (float)KNN);
            feat[t][INCH + PDIM + c] = fmaxf(mxA[c], mx);
        }
        __syncthreads();
    }

    // out[i, c] = relu( feat[i,:] @ Wo[:, c] + bo[c] ), c = tid
    const int c = tid;
    float acc[16];
    #pragma unroll
    for (int t = 0; t < 16; t++) acc[t] = bo[c];
    for (int kk = 0; kk < 2 * PDIM + INCH; kk += 4) {
        const float w0 = Wo[(size_t)(kk + 0) * OUTCH + c];
        const float w1 = Wo[(size_t)(kk + 1) * OUTCH + c];
        const float w2 = Wo[(size_t)(kk + 2) * OUTCH + c];
        const float w3 = Wo[(size_t)(kk + 3) * OUTCH + c];
        #pragma unroll
        for (int t = 0; t < 16; t++) {
            const float4 f = *(const float4*)&feat[t][kk];
            acc[t] = __fmaf_rn(f.x, w0, acc[t]);
            acc[t] = __fmaf_rn(f.y, w1, acc[t]);
            acc[t] = __fmaf_rn(f.z, w2, acc[t]);
            acc[t] = __fmaf_rn(f.w, w3, acc[t]);
        }
    }
    #pragma unroll
    for (int t = 0; t < 16; t++)
        out[(size_t)(base + t) * OUTCH + c] = fmaxf(acc[t], 0.0f);
}

// ---------------- K4: assemble remaining output regions ----------------
// d_out layout: [out N*128][idx N*50][distsq N*50][space N*4]
__global__ void k4_pack(float* __restrict__ out, int N) {
    const int total = N * KNN * 2 + N * SDIM;
    for (int e = blockIdx.x * blockDim.x + threadIdx.x; e < total;
         e += gridDim.x * blockDim.x) {
        if (e < N * KNN) {
            out[(size_t)N * 128 + e] = (float)g_idx[e];
        } else if (e < 2 * N * KNN) {
            out[(size_t)N * 178 + (e - N * KNN)] = g_d2[e - N * KNN];
        } else {
            out[(size_t)N * 228 + (e - 2 * N * KNN)] = g_space[e - 2 * N * KNN];
        }
    }
}

// ---------------- launch ----------------
extern "C" void kernel_launch(void* const* d_in, const int* in_sizes, int n_in,
                              void* d_out, int out_size) {
    const float* x  = (const float*)d_in[0];
    // d_in[1] = row_splits (equal segments, unused; reference ignores values too)
    const float* Ws = (const float*)d_in[2];
    const float* bs = (const float*)d_in[3];
    const float* Wp = (const float*)d_in[4];
    const float* bp = (const float*)d_in[5];
    const float* Wo = (const float*)d_in[6];
    const float* bo = (const float*)d_in[7];

    const int N = in_sizes[0] / INCH;   // 16384
    float* out = (float*)d_out;

    k1_project<<<N / 16, 256>>>(x, Ws, bs, Wp, bp);

    cudaFuncSetAttribute(k2_knn, cudaFuncAttributeMaxDynamicSharedMemorySize, K2_SMEM);
    k2_knn<<<N / 8, 256, K2_SMEM>>>();

    k3_aggregate<<<N / 16, 128>>>(x, Wo, bo, out);

    if (out_size >= N * 232) {
        k4_pack<<<2048, 256>>>(out, N);
    }
    (void)n_in; (void)in_sizes;
}

// round 4
// speedup vs baseline: 2.4398x; 2.4398x over previous
#include <cuda_runtime.h>
#include <cuda_bf16.h>
#include <math.h>

#define FULLMASK 0xFFFFFFFFu

// Problem constants (fixed by the dataset)
#define NMAX   16384
#define INCH   128
#define SDIM   4
#define PDIM   64
#define OUTCH  128
#define KNN    50
#define NPER   4096   // nodes per segment (16384 / 4 splits)
#define CAP    128    // pass-2 collection buffer per query

// ---------------- device scratch (no allocation allowed) ----------------
__device__ float g_space[NMAX * SDIM];
__device__ float g_prop [NMAX * PDIM];
__device__ int   g_idx  [NMAX * KNN];
__device__ float g_w    [NMAX * KNN];   // exp(-10*d2), precomputed for k3

// Bit-exact replication of reference arithmetic (do not touch):
__device__ __forceinline__ float xla_sq4(float4 c) {
    return __fadd_rn(__fadd_rn(__fadd_rn(__fmul_rn(c.x, c.x), __fmul_rn(c.y, c.y)),
                               __fmul_rn(c.z, c.z)),
                     __fmul_rn(c.w, c.w));
}
__device__ __forceinline__ float cublas_dot4(float4 a, float4 b) {
    return __fmaf_rn(a.w, b.w, __fmaf_rn(a.z, b.z, __fmaf_rn(a.y, b.y, __fmul_rn(a.x, b.x))));
}
__device__ __forceinline__ float d2f(float4 cq, float sqq, float4 cj, float sqj) {
    const float dot = cublas_dot4(cq, cj);
    const float t   = __fadd_rn(sqq, sqj);
    return fmaxf(__fadd_rn(t, __fmul_rn(-2.0f, dot)), 0.0f);
}

// ---------------- K1: space = x@Ws + bs ; prop = x@Wp + bp ----------------
// space emulates cuBLAS skinny-gemm "sliced1x4" (validated in round 3).
__global__ void k1_project(const float* __restrict__ x,
                           const float* __restrict__ Ws, const float* __restrict__ bs,
                           const float* __restrict__ Wp, const float* __restrict__ bp,
                           float* __restrict__ out, int N) {
    __shared__ float sWp[INCH * PDIM];
    __shared__ float sWs[INCH * SDIM];
    __shared__ float sx[16 * INCH];
    const int tid = threadIdx.x;
    for (int i = tid; i < INCH * PDIM; i += 256) sWp[i] = Wp[i];
    for (int i = tid; i < INCH * SDIM; i += 256) sWs[i] = Ws[i];
    const int base = blockIdx.x * 16;
    for (int i = tid; i < 16 * INCH; i += 256) sx[i] = x[(size_t)base * INCH + i];
    __syncthreads();

    for (int o = tid; o < 16 * (PDIM + SDIM); o += 256) {
        const int node = o / (PDIM + SDIM);
        const int c    = o - node * (PDIM + SDIM);
        const float* xr = &sx[node * INCH];
        const int gn = base + node;
        if (c < PDIM) {
            float acc = bp[c];
            #pragma unroll 8
            for (int kk = 0; kk < INCH; kk++) acc = __fmaf_rn(xr[kk], sWp[kk * PDIM + c], acc);
            g_prop[(size_t)gn * PDIM + c] = acc;
        } else {
            const int cs = c - PDIM;
            float s[4];
            #pragma unroll
            for (int sl = 0; sl < 4; sl++) {
                float acc = 0.0f;
                const int k0 = sl * 32;
                #pragma unroll
                for (int kk = 0; kk < 32; kk++)
                    acc = __fmaf_rn(xr[k0 + kk], sWs[(k0 + kk) * SDIM + cs], acc);
                s[sl] = acc;
            }
            const float g = __fadd_rn(__fadd_rn(__fadd_rn(s[0], s[1]), s[2]), s[3]);
            const float v = __fadd_rn(g, bs[cs]);
            g_space[(size_t)gn * SDIM + cs] = v;
            out[(size_t)N * 228 + (size_t)gn * SDIM + cs] = v;   // space output region
        }
    }
}

// ---------------- K2: exact KNN via threshold-bound + compaction ----------------
// 256 threads = 8 warps; warp handles 2 queries; 16 queries/block.
// Dynamic smem: coords float4[4096] (64KB) | sq float[4096] (16KB) | buf u64[16][CAP] (16KB)
#define K2_SMEM (NPER*16 + NPER*4 + 16*CAP*8)

__device__ __forceinline__ void k2_write(unsigned long long key, int rank, int gq,
                                         int segBase, float* __restrict__ out, int N) {
    const int j = (int)(key & 0xFFFFFFFFull);
    const float v = __uint_as_float((unsigned)(key >> 32));
    const int gi = segBase + j;
    g_idx[(size_t)gq * KNN + rank] = gi;
    g_w  [(size_t)gq * KNN + rank] = expf(-10.0f * v);
    out[(size_t)N * 128 + (size_t)gq * KNN + rank] = (float)gi;  // neighbor_idx region
    out[(size_t)N * 178 + (size_t)gq * KNN + rank] = v;          // distsq region
}

__device__ __forceinline__ float select49(const unsigned long long* __restrict__ buf,
                                          float a0, float a1, float a2, int lane) {
    const unsigned long long k0 = ((unsigned long long)__float_as_uint(a0) << 32) | (unsigned)(lane * 3 + 0);
    const unsigned long long k1 = ((unsigned long long)__float_as_uint(a1) << 32) | (unsigned)(lane * 3 + 1);
    const unsigned long long k2 = ((unsigned long long)__float_as_uint(a2) << 32) | (unsigned)(lane * 3 + 2);
    int r0 = 0, r1 = 0, r2 = 0;
    for (int n = 0; n < 96; n++) {
        const unsigned long long u = buf[n];
        r0 += (u < k0); r1 += (u < k1); r2 += (u < k2);
    }
    const bool h = (r0 == 49) || (r1 == 49) || (r2 == 49);
    const float vh = (r0 == 49) ? a0 : ((r1 == 49) ? a1 : a2);
    const unsigned m = __ballot_sync(FULLMASK, h);
    return __shfl_sync(FULLMASK, vh, __ffs(m) - 1);
}

__device__ void k2_finalize(unsigned long long* __restrict__ buf, unsigned cnt, int gq,
                            float4 cq, float sqq, int segBase, int lane,
                            const float4* __restrict__ sC, const float* __restrict__ sSq,
                            float* __restrict__ out, int N) {
    if (cnt <= CAP) {
        for (int m = lane; m < (int)cnt; m += 32) {
            const unsigned long long key = buf[m];
            int rank = 0;
            for (int n = 0; n < (int)cnt; n++) rank += (buf[n] < key);
            if (rank < KNN) k2_write(key, rank, gq, segBase, out, N);
        }
    } else {
        // Exact deterministic fallback (practically never taken): serial min-extraction.
        long long prev = -1;
        for (int r = 0; r < KNN; r++) {
            unsigned long long best = ~0ull;
            for (int j = lane; j < NPER; j += 32) {
                const float v = d2f(cq, sqq, sC[j], sSq[j]);
                const unsigned long long key =
                    ((unsigned long long)__float_as_uint(v) << 32) | (unsigned)j;
                if ((long long)key > prev && key < best) best = key;
            }
            #pragma unroll
            for (int off = 16; off; off >>= 1) {
                const unsigned long long o = __shfl_xor_sync(FULLMASK, best, off);
                if (o < best) best = o;
            }
            if (lane == 0) k2_write(best, r, gq, segBase, out, N);
            prev = (long long)best;
        }
    }
}

__global__ void k2_knn(float* __restrict__ out, int N) {
    extern __shared__ unsigned char dsm[];
    float4*             sC   = (float4*)dsm;                          // 64 KB
    float*              sSq  = (float*)(dsm + NPER * 16);             // 16 KB
    unsigned long long* sBuf = (unsigned long long*)(dsm + NPER * 20);// 16 KB

    const int tid = threadIdx.x;
    const int w = tid >> 5, lane = tid & 31;
    const int qBase = blockIdx.x * 16;
    const int segBase = qBase & ~(NPER - 1);

    for (int j = tid; j < NPER; j += 256) {
        const float4 c = *(const float4*)&g_space[(size_t)(segBase + j) * 4];
        sC[j] = c;
        sSq[j] = xla_sq4(c);
    }
    __syncthreads();

    const int q0 = qBase + 2 * w;
    const int ql = q0 - segBase;
    const float4 cq0 = sC[ql];     const float sq0 = sSq[ql];
    const float4 cq1 = sC[ql + 1]; const float sq1 = sSq[ql + 1];
    unsigned long long* buf0 = sBuf + (size_t)(2 * w) * CAP;
    unsigned long long* buf1 = buf0 + CAP;

    // ---- Pass 1: per-lane top-3 for both queries ----
    float a0 = INFINITY, a1 = INFINITY, a2 = INFINITY;
    float b0 = INFINITY, b1 = INFINITY, b2 = INFINITY;
    for (int j = lane; j < NPER; j += 32) {
        const float4 cj = sC[j]; const float sj = sSq[j];
        const float v0 = d2f(cq0, sq0, cj, sj);
        const float v1 = d2f(cq1, sq1, cj, sj);
        a2 = fminf(a2, fmaxf(a1, v0)); a1 = fminf(a1, fmaxf(a0, v0)); a0 = fminf(a0, v0);
        b2 = fminf(b2, fmaxf(b1, v1)); b1 = fminf(b1, fmaxf(b0, v1)); b0 = fminf(b0, v1);
    }

    // ---- Upper-bound threshold = 50th smallest of the 96 candidates ----
    buf0[lane * 3 + 0] = ((unsigned long long)__float_as_uint(a0) << 32) | (unsigned)(lane * 3 + 0);
    buf0[lane * 3 + 1] = ((unsigned long long)__float_as_uint(a1) << 32) | (unsigned)(lane * 3 + 1);
    buf0[lane * 3 + 2] = ((unsigned long long)__float_as_uint(a2) << 32) | (unsigned)(lane * 3 + 2);
    buf1[lane * 3 + 0] = ((unsigned long long)__float_as_uint(b0) << 32) | (unsigned)(lane * 3 + 0);
    buf1[lane * 3 + 1] = ((unsigned long long)__float_as_uint(b1) << 32) | (unsigned)(lane * 3 + 1);
    buf1[lane * 3 + 2] = ((unsigned long long)__float_as_uint(b2) << 32) | (unsigned)(lane * 3 + 2);
    __syncwarp();
    const float T0 = select49(buf0, a0, a1, a2, lane);
    const float T1 = select49(buf1, b0, b1, b2, lane);
    __syncwarp();

    // ---- Pass 2: ordered compaction of all d2 <= T ----
    unsigned c0 = 0, c1 = 0;
    const unsigned lm = (1u << lane) - 1u;
    for (int base = 0; base < NPER; base += 32) {
        const int j = base + lane;
        const float4 cj = sC[j]; const float sj = sSq[j];
        const float v0 = d2f(cq0, sq0, cj, sj);
        const float v1 = d2f(cq1, sq1, cj, sj);
        const bool t0 = (v0 <= T0), t1 = (v1 <= T1);
        const unsigned m0 = __ballot_sync(FULLMASK, t0);
        const unsigned m1 = __ballot_sync(FULLMASK, t1);
        if (t0) {
            const unsigned p = c0 + __popc(m0 & lm);
            if (p < CAP) buf0[p] = ((unsigned long long)__float_as_uint(v0) << 32) | (unsigned)j;
        }
        if (t1) {
            const unsigned p = c1 + __popc(m1 & lm);
            if (p < CAP) buf1[p] = ((unsigned long long)__float_as_uint(v1) << 32) | (unsigned)j;
        }
        c0 += __popc(m0); c1 += __popc(m1);
    }
    __syncwarp();

    // ---- Final exact rank-sort + writes ----
    k2_finalize(buf0, c0, q0,     cq0, sq0, segBase, lane, sC, sSq, out, N);
    k2_finalize(buf1, c1, q0 + 1, cq1, sq1, segBase, lane, sC, sSq, out, N);
}

// ---------------- K3: gather + mean/max + output GEMM + relu ----------------
__global__ void k3_aggregate(const float* __restrict__ x,
                             const float* __restrict__ Wo, const float* __restrict__ bo,
                             float* __restrict__ out) {
    __shared__ __align__(16) float feat[16][2 * PDIM + INCH];
    __shared__ float warr[KNN];
    __shared__ int   gidx[KNN];
    __shared__ float accA[PDIM], mxA[PDIM];

    const int tid = threadIdx.x;
    const int base = blockIdx.x * 16;

    for (int t = 0; t < 16; t++) {
        const int i = base + t;
        if (tid < KNN) {
            warr[tid] = g_w  [(size_t)i * KNN + tid];
            gidx[tid] = g_idx[(size_t)i * KNN + tid];
        }
        feat[t][tid] = x[(size_t)i * INCH + tid];
        __syncthreads();

        const int half = tid >> 6, c = tid & 63;
        float acc = 0.0f, mx = -INFINITY;
        for (int r = half; r < KNN; r += 2) {
            const float v = g_prop[(size_t)gidx[r] * PDIM + c] * warr[r];
            acc += v; mx = fmaxf(mx, v);
        }
        if (half == 0) { accA[c] = acc; mxA[c] = mx; }
        __syncthreads();
        if (half == 1) {
            feat[t][INCH + c]        = (accA[c] + acc) * (1.0f / (float)KNN);
            feat[t][INCH + PDIM + c] = fmaxf(mxA[c], mx);
        }
        __syncthreads();
    }

    const int c = tid;
    float acc[16];
    #pragma unroll
    for (int t = 0; t < 16; t++) acc[t] = bo[c];
    for (int kk = 0; kk < 2 * PDIM + INCH; kk += 4) {
        const float w0 = Wo[(size_t)(kk + 0) * OUTCH + c];
        const float w1 = Wo[(size_t)(kk + 1) * OUTCH + c];
        const float w2 = Wo[(size_t)(kk + 2) * OUTCH + c];
        const float w3 = Wo[(size_t)(kk + 3) * OUTCH + c];
        #pragma unroll
        for (int t = 0; t < 16; t++) {
            const float4 f = *(const float4*)&feat[t][kk];
            acc[t] = __fmaf_rn(f.x, w0, acc[t]);
            acc[t] = __fmaf_rn(f.y, w1, acc[t]);
            acc[t] = __fmaf_rn(f.z, w2, acc[t]);
            acc[t] = __fmaf_rn(f.w, w3, acc[t]);
        }
    }
    #pragma unroll
    for (int t = 0; t < 16; t++)
        out[(size_t)(base + t) * OUTCH + c] = fmaxf(acc[t], 0.0f);
}

// ---------------- launch ----------------
extern "C" void kernel_launch(void* const* d_in, const int* in_sizes, int n_in,
                              void* d_out, int out_size) {
    const float* x  = (const float*)d_in[0];
    const float* Ws = (const float*)d_in[2];
    const float* bs = (const float*)d_in[3];
    const float* Wp = (const float*)d_in[4];
    const float* bp = (const float*)d_in[5];
    const float* Wo = (const float*)d_in[6];
    const float* bo = (const float*)d_in[7];

    const int N = in_sizes[0] / INCH;   // 16384
    float* out = (float*)d_out;

    k1_project<<<N / 16, 256>>>(x, Ws, bs, Wp, bp, out, N);

    cudaFuncSetAttribute(k2_knn, cudaFuncAttributeMaxDynamicSharedMemorySize, K2_SMEM);
    k2_knn<<<N / 16, 256, K2_SMEM>>>(out, N);

    k3_aggregate<<<N / 16, 128>>>(x, Wo, bo, out);

    (void)n_in; (void)in_sizes; (void)out_size;
}

// round 5
// speedup vs baseline: 2.7833x; 1.1408x over previous
#include <cuda_runtime.h>
#include <cuda_bf16.h>
#include <math.h>

#define FULLMASK 0xFFFFFFFFu

// Problem constants (fixed by the dataset)
#define NMAX   16384
#define INCH   128
#define SDIM   4
#define PDIM   64
#define OUTCH  128
#define KNN    50
#define NPER   4096   // nodes per segment (16384 / 4 splits)
#define CAP    128    // pass-2 collection buffer per query

// ---------------- device scratch (no allocation allowed) ----------------
__device__ float g_space[NMAX * SDIM];
__device__ float g_prop [NMAX * PDIM];
__device__ int   g_idx  [NMAX * KNN];
__device__ float g_w    [NMAX * KNN];   // exp(-10*d2), precomputed for k3

// Bit-exact replication of reference arithmetic (do not touch):
__device__ __forceinline__ float xla_sq4(float4 c) {
    return __fadd_rn(__fadd_rn(__fadd_rn(__fmul_rn(c.x, c.x), __fmul_rn(c.y, c.y)),
                               __fmul_rn(c.z, c.z)),
                     __fmul_rn(c.w, c.w));
}
__device__ __forceinline__ float cublas_dot4(float4 a, float4 b) {
    return __fmaf_rn(a.w, b.w, __fmaf_rn(a.z, b.z, __fmaf_rn(a.y, b.y, __fmul_rn(a.x, b.x))));
}
__device__ __forceinline__ float d2f(float4 cq, float sqq, float4 cj, float sqj) {
    const float dot = cublas_dot4(cq, cj);
    const float t   = __fadd_rn(sqq, sqj);
    return fmaxf(__fadd_rn(t, __fmul_rn(-2.0f, dot)), 0.0f);
}

// ---------------- K1: space = x@Ws + bs ; prop = x@Wp + bp ----------------
// 64 nodes/block, 256 threads. Prop uses a 4-node x 4-channel register tile
// with float4 smem reads (2 B of LDS per FMA). Space keeps the exact
// sliced1x4 serial chain validated in round 3 (bit-identical coords).
__global__ __launch_bounds__(256) void k1_project(
        const float* __restrict__ x,
        const float* __restrict__ Ws, const float* __restrict__ bs,
        const float* __restrict__ Wp, const float* __restrict__ bp,
        float* __restrict__ out, int N) {
    __shared__ __align__(16) float sx [64 * INCH];        // 32 KB
    __shared__ __align__(16) float sWp[INCH * PDIM];      // 32 KB
    __shared__ float sWs[INCH * SDIM];                    //  2 KB
    const int tid = threadIdx.x;
    const int base = blockIdx.x * 64;

    for (int i = tid * 4; i < 64 * INCH; i += 1024)
        *(float4*)&sx[i] = *(const float4*)&x[(size_t)base * INCH + i];
    for (int i = tid * 4; i < INCH * PDIM; i += 1024)
        *(float4*)&sWp[i] = *(const float4*)&Wp[i];
    for (int i = tid; i < INCH * SDIM; i += 256) sWs[i] = Ws[i];
    __syncthreads();

    // ---- prop: register tile 4 nodes x 4 channels ----
    {
        const int cg = (tid & 15) * 4;          // c0
        const int ng = (tid >> 4) * 4;          // n0
        float acc[4][4];
        #pragma unroll
        for (int i = 0; i < 4; i++) {
            const float4 b4 = *(const float4*)&bp[cg];
            acc[i][0] = b4.x; acc[i][1] = b4.y; acc[i][2] = b4.z; acc[i][3] = b4.w;
        }
        for (int kk = 0; kk < INCH; kk += 4) {
            float4 xv[4];
            #pragma unroll
            for (int i = 0; i < 4; i++) xv[i] = *(const float4*)&sx[(ng + i) * INCH + kk];
            #pragma unroll
            for (int q = 0; q < 4; q++) {
                const float4 w4 = *(const float4*)&sWp[(kk + q) * PDIM + cg];
                #pragma unroll
                for (int i = 0; i < 4; i++) {
                    const float xs = (q == 0) ? xv[i].x : (q == 1) ? xv[i].y
                                   : (q == 2) ? xv[i].z : xv[i].w;
                    acc[i][0] = __fmaf_rn(xs, w4.x, acc[i][0]);
                    acc[i][1] = __fmaf_rn(xs, w4.y, acc[i][1]);
                    acc[i][2] = __fmaf_rn(xs, w4.z, acc[i][2]);
                    acc[i][3] = __fmaf_rn(xs, w4.w, acc[i][3]);
                }
            }
        }
        #pragma unroll
        for (int i = 0; i < 4; i++) {
            float4 r; r.x = acc[i][0]; r.y = acc[i][1]; r.z = acc[i][2]; r.w = acc[i][3];
            *(float4*)&g_prop[(size_t)(base + ng + i) * PDIM + cg] = r;
        }
    }

    // ---- space: exact sliced1x4 chain, one thread per (node, cs) ----
    {
        const int node = tid >> 2, cs = tid & 3;
        const float* xr = &sx[node * INCH];
        float s[4];
        #pragma unroll
        for (int sl = 0; sl < 4; sl++) {
            float acc = 0.0f;
            const int k0 = sl * 32;
            #pragma unroll
            for (int kk = 0; kk < 32; kk++)
                acc = __fmaf_rn(xr[k0 + kk], sWs[(k0 + kk) * SDIM + cs], acc);
            s[sl] = acc;
        }
        const float g = __fadd_rn(__fadd_rn(__fadd_rn(s[0], s[1]), s[2]), s[3]);
        const float v = __fadd_rn(g, bs[cs]);
        const int gn = base + node;
        g_space[(size_t)gn * SDIM + cs] = v;
        out[(size_t)N * 228 + (size_t)gn * SDIM + cs] = v;   // space output region
    }
}

// ---------------- K2: exact KNN via threshold-bound + compaction ----------------
// 256 threads = 8 warps; warp handles 2 queries; 16 queries/block.
#define K2_SMEM (NPER*16 + NPER*4 + 16*CAP*8)

__device__ __forceinline__ void k2_write(unsigned long long key, int rank, int gq,
                                         int segBase, float* __restrict__ out, int N) {
    const int j = (int)(key & 0xFFFFFFFFull);
    const float v = __uint_as_float((unsigned)(key >> 32));
    const int gi = segBase + j;
    g_idx[(size_t)gq * KNN + rank] = gi;
    g_w  [(size_t)gq * KNN + rank] = expf(-10.0f * v);
    out[(size_t)N * 128 + (size_t)gq * KNN + rank] = (float)gi;  // neighbor_idx region
    out[(size_t)N * 178 + (size_t)gq * KNN + rank] = v;          // distsq region
}

__device__ __forceinline__ float select49(const unsigned long long* __restrict__ buf,
                                          float a0, float a1, float a2, int lane) {
    const unsigned long long k0 = ((unsigned long long)__float_as_uint(a0) << 32) | (unsigned)(lane * 3 + 0);
    const unsigned long long k1 = ((unsigned long long)__float_as_uint(a1) << 32) | (unsigned)(lane * 3 + 1);
    const unsigned long long k2 = ((unsigned long long)__float_as_uint(a2) << 32) | (unsigned)(lane * 3 + 2);
    int r0 = 0, r1 = 0, r2 = 0;
    for (int n = 0; n < 96; n++) {
        const unsigned long long u = buf[n];
        r0 += (u < k0); r1 += (u < k1); r2 += (u < k2);
    }
    const bool h = (r0 == 49) || (r1 == 49) || (r2 == 49);
    const float vh = (r0 == 49) ? a0 : ((r1 == 49) ? a1 : a2);
    const unsigned m = __ballot_sync(FULLMASK, h);
    return __shfl_sync(FULLMASK, vh, __ffs(m) - 1);
}

__device__ void k2_finalize(unsigned long long* __restrict__ buf, unsigned cnt, int gq,
                            float4 cq, float sqq, int segBase, int lane,
                            const float4* __restrict__ sC, const float* __restrict__ sSq,
                            float* __restrict__ out, int N) {
    if (cnt >= KNN && cnt <= CAP) {
        for (int m = lane; m < (int)cnt; m += 32) {
            const unsigned long long key = buf[m];
            int rank = 0;
            for (int n = 0; n < (int)cnt; n++) rank += (buf[n] < key);
            if (rank < KNN) k2_write(key, rank, gq, segBase, out, N);
        }
    } else {
        // Exact deterministic fallback (practically never taken).
        long long prev = -1;
        for (int r = 0; r < KNN; r++) {
            unsigned long long best = ~0ull;
            for (int j = lane; j < NPER; j += 32) {
                const float v = d2f(cq, sqq, sC[j], sSq[j]);
                const unsigned long long key =
                    ((unsigned long long)__float_as_uint(v) << 32) | (unsigned)j;
                if ((long long)key > prev && key < best) best = key;
            }
            #pragma unroll
            for (int off = 16; off; off >>= 1) {
                const unsigned long long o = __shfl_xor_sync(FULLMASK, best, off);
                if (o < best) best = o;
            }
            if (lane == 0) k2_write(best, r, gq, segBase, out, N);
            prev = (long long)best;
        }
    }
}

__global__ void k2_knn(float* __restrict__ out, int N) {
    extern __shared__ unsigned char dsm[];
    float4*             sC   = (float4*)dsm;                          // 64 KB
    float*              sSq  = (float*)(dsm + NPER * 16);             // 16 KB
    unsigned long long* sBuf = (unsigned long long*)(dsm + NPER * 20);// 16 KB

    const int tid = threadIdx.x;
    const int w = tid >> 5, lane = tid & 31;
    const int qBase = blockIdx.x * 16;
    const int segBase = qBase & ~(NPER - 1);

    for (int j = tid; j < NPER; j += 256) {
        const float4 c = *(const float4*)&g_space[(size_t)(segBase + j) * 4];
        sC[j] = c;
        sSq[j] = xla_sq4(c);
    }
    __syncthreads();

    const int q0 = qBase + 2 * w;
    const int ql = q0 - segBase;
    const float4 cq0 = sC[ql];     const float sq0 = sSq[ql];
    const float4 cq1 = sC[ql + 1]; const float sq1 = sSq[ql + 1];
    unsigned long long* buf0 = sBuf + (size_t)(2 * w) * CAP;
    unsigned long long* buf1 = buf0 + CAP;

    // ---- Pass 1: per-lane top-3 for both queries ----
    float a0 = INFINITY, a1 = INFINITY, a2 = INFINITY;
    float b0 = INFINITY, b1 = INFINITY, b2 = INFINITY;
    for (int j = lane; j < NPER; j += 32) {
        const float4 cj = sC[j]; const float sj = sSq[j];
        const float v0 = d2f(cq0, sq0, cj, sj);
        const float v1 = d2f(cq1, sq1, cj, sj);
        a2 = fminf(a2, fmaxf(a1, v0)); a1 = fminf(a1, fmaxf(a0, v0)); a0 = fminf(a0, v0);
        b2 = fminf(b2, fmaxf(b1, v1)); b1 = fminf(b1, fmaxf(b0, v1)); b0 = fminf(b0, v1);
    }

    // ---- Upper-bound threshold = 50th smallest of the 96 candidates ----
    buf0[lane * 3 + 0] = ((unsigned long long)__float_as_uint(a0) << 32) | (unsigned)(lane * 3 + 0);
    buf0[lane * 3 + 1] = ((unsigned long long)__float_as_uint(a1) << 32) | (unsigned)(lane * 3 + 1);
    buf0[lane * 3 + 2] = ((unsigned long long)__float_as_uint(a2) << 32) | (unsigned)(lane * 3 + 2);
    buf1[lane * 3 + 0] = ((unsigned long long)__float_as_uint(b0) << 32) | (unsigned)(lane * 3 + 0);
    buf1[lane * 3 + 1] = ((unsigned long long)__float_as_uint(b1) << 32) | (unsigned)(lane * 3 + 1);
    buf1[lane * 3 + 2] = ((unsigned long long)__float_as_uint(b2) << 32) | (unsigned)(lane * 3 + 2);
    __syncwarp();
    const float T0 = select49(buf0, a0, a1, a2, lane);
    const float T1 = select49(buf1, b0, b1, b2, lane);
    __syncwarp();

    // ---- Pass 2: ordered compaction of all d2 <= T ----
    unsigned c0 = 0, c1 = 0;
    const unsigned lm = (1u << lane) - 1u;
    for (int base = 0; base < NPER; base += 32) {
        const int j = base + lane;
        const float4 cj = sC[j]; const float sj = sSq[j];
        const float v0 = d2f(cq0, sq0, cj, sj);
        const float v1 = d2f(cq1, sq1, cj, sj);
        const bool t0 = (v0 <= T0), t1 = (v1 <= T1);
        const unsigned m0 = __ballot_sync(FULLMASK, t0);
        const unsigned m1 = __ballot_sync(FULLMASK, t1);
        if (t0) {
            const unsigned p = c0 + __popc(m0 & lm);
            if (p < CAP) buf0[p] = ((unsigned long long)__float_as_uint(v0) << 32) | (unsigned)j;
        }
        if (t1) {
            const unsigned p = c1 + __popc(m1 & lm);
            if (p < CAP) buf1[p] = ((unsigned long long)__float_as_uint(v1) << 32) | (unsigned)j;
        }
        c0 += __popc(m0); c1 += __popc(m1);
    }
    __syncwarp();

    k2_finalize(buf0, c0, q0,     cq0, sq0, segBase, lane, sC, sSq, out, N);
    k2_finalize(buf1, c1, q0 + 1, cq1, sq1, segBase, lane, sC, sSq, out, N);
}

// ---------------- K3: gather + mean/max + output GEMM + relu ----------------
// 32 nodes/block, 256 threads; gather runs 4 nodes concurrently.
__global__ __launch_bounds__(256) void k3_aggregate(
        const float* __restrict__ x,
        const float* __restrict__ Wo, const float* __restrict__ bo,
        float* __restrict__ out) {
    __shared__ __align__(16) float feat[32][2 * PDIM + INCH];   // 32 KB
    __shared__ float swarr[32 * KNN];                            // 6.4 KB
    __shared__ int   sgidx[32 * KNN];                            // 6.4 KB

    const int tid = threadIdx.x;
    const int base = blockIdx.x * 32;

    // Prefetch x rows and neighbor tables.
    for (int i = tid * 4; i < 32 * INCH; i += 1024) {
        const int node = i >> 7, c = i & 127;
        *(float4*)&feat[node][c] = *(const float4*)&x[(size_t)(base + node) * INCH + c];
    }
    for (int i = tid; i < 32 * KNN; i += 256) {
        swarr[i] = g_w  [(size_t)base * KNN + i];
        sgidx[i] = g_idx[(size_t)base * KNN + i];
    }
    __syncthreads();

    // Gather: 4 nodes in parallel, 64 threads (=64 channels) per node.
    {
        const int ns = tid >> 6, c = tid & 63;
        for (int nn = ns; nn < 32; nn += 4) {
            const float* wr = &swarr[nn * KNN];
            const int*   ir = &sgidx[nn * KNN];
            float acc = 0.0f, mx = -INFINITY;
            #pragma unroll 5
            for (int r = 0; r < KNN; r++) {
                const float v = g_prop[(size_t)ir[r] * PDIM + c] * wr[r];
                acc += v; mx = fmaxf(mx, v);
            }
            feat[nn][INCH + c]        = acc * (1.0f / (float)KNN);
            feat[nn][INCH + PDIM + c] = mx;
        }
    }
    __syncthreads();

    // GEMM: c = tid%128; half = tid/128 handles 16 nodes.
    const int c = tid & 127;
    const int t0 = (tid >> 7) * 16;
    float acc[16];
    #pragma unroll
    for (int t = 0; t < 16; t++) acc[t] = bo[c];
    for (int kk = 0; kk < 2 * PDIM + INCH; kk += 4) {
        const float w0 = Wo[(size_t)(kk + 0) * OUTCH + c];
        const float w1 = Wo[(size_t)(kk + 1) * OUTCH + c];
        const float w2 = Wo[(size_t)(kk + 2) * OUTCH + c];
        const float w3 = Wo[(size_t)(kk + 3) * OUTCH + c];
        #pragma unroll
        for (int t = 0; t < 16; t++) {
            const float4 f = *(const float4*)&feat[t0 + t][kk];
            acc[t] = __fmaf_rn(f.x, w0, acc[t]);
            acc[t] = __fmaf_rn(f.y, w1, acc[t]);
            acc[t] = __fmaf_rn(f.z, w2, acc[t]);
            acc[t] = __fmaf_rn(f.w, w3, acc[t]);
        }
    }
    #pragma unroll
    for (int t = 0; t < 16; t++)
        out[(size_t)(base + t0 + t) * OUTCH + c] = fmaxf(acc[t], 0.0f);
}

// ---------------- launch ----------------
extern "C" void kernel_launch(void* const* d_in, const int* in_sizes, int n_in,
                              void* d_out, int out_size) {
    const float* x  = (const float*)d_in[0];
    const float* Ws = (const float*)d_in[2];
    const float* bs = (const float*)d_in[3];
    const float* Wp = (const float*)d_in[4];
    const float* bp = (const float*)d_in[5];
    const float* Wo = (const float*)d_in[6];
    const float* bo = (const float*)d_in[7];

    const int N = in_sizes[0] / INCH;   // 16384
    float* out = (float*)d_out;

    k1_project<<<N / 64, 256>>>(x, Ws, bs, Wp, bp, out, N);

    cudaFuncSetAttribute(k2_knn, cudaFuncAttributeMaxDynamicSharedMemorySize, K2_SMEM);
    k2_knn<<<N / 16, 256, K2_SMEM>>>(out, N);

    k3_aggregate<<<N / 32, 256>>>(x, Wo, bo, out);

    (void)n_in; (void)in_sizes; (void)out_size;
}